// round 6
// baseline (speedup 1.0000x reference)
#include <cuda_runtime.h>
#include <cstdint>

// Masked per-graph mean pooling — barrier-free version.
// Inputs (metadata order):
//   d_in[0]: node_embeddings float32 [B*N, D] = [4096*64, 256]
//   d_in[1]: op_idx          int32   [B, N]   = [4096, 64]
// Output: float32 [B, D] = [4096, 256]
//
// out[b, :] = sum_{n: op[b,n]!=5} h[b,n,:] / max(count, 1)
//
// Shape: one CTA per graph, 64 threads; thread t owns float4 column t and
// walks all 64 rows. op[b*64+r] is warp-uniform per step (all lanes share r),
// so the mask is a broadcast L1-hit load — no smem, no __syncthreads anywhere.
// Per-thread MLP depth 64; per-iteration the CTA reads one contiguous 1 KB row.

#define SKIP_OP 5
#define NNODES  64
#define DIM     256
#define DIM4    (DIM / 4)   // 64 float4 per row

__global__ __launch_bounds__(64, 24)
void readout_kernel(const float* __restrict__ h,
                    const int* __restrict__ op,
                    float* __restrict__ out)
{
    const int b   = blockIdx.x;
    const int col = threadIdx.x;            // float4 column 0..63

    const float4* hp = reinterpret_cast<const float4*>(
        h + (size_t)b * NNODES * DIM);
    const int* opb = op + (size_t)b * NNODES;

    float4 acc = make_float4(0.f, 0.f, 0.f, 0.f);
    float  cnt = 0.f;

#pragma unroll 16
    for (int r = 0; r < NNODES; r++) {
        const float  m = (__ldg(&opb[r]) != SKIP_OP) ? 1.0f : 0.0f;  // warp-uniform
        const float4 v = __ldcs(&hp[r * DIM4 + col]);                // streaming
        cnt  += m;
        acc.x = fmaf(m, v.x, acc.x);
        acc.y = fmaf(m, v.y, acc.y);
        acc.z = fmaf(m, v.z, acc.z);
        acc.w = fmaf(m, v.w, acc.w);
    }

    const float inv = 1.0f / fmaxf(cnt, 1.0f);
    acc.x *= inv; acc.y *= inv; acc.z *= inv; acc.w *= inv;

    __stcs(&reinterpret_cast<float4*>(out + (size_t)b * DIM)[col], acc);
}

extern "C" void kernel_launch(void* const* d_in, const int* in_sizes, int n_in,
                              void* d_out, int out_size)
{
    const float* h  = (const float*)d_in[0];
    const int*   op = (const int*)d_in[1];
    float*       o  = (float*)d_out;

    const int B = in_sizes[1] / NNODES;   // op_idx has B*N elements

    readout_kernel<<<B, 64>>>(h, op, o);
}

// round 7
// speedup vs baseline: 1.1427x; 1.1427x over previous
#include <cuda_runtime.h>
#include <cstdint>

// Masked per-graph mean pooling — column-split version.
// Inputs (metadata order):
//   d_in[0]: node_embeddings float32 [B*N, D] = [4096*64, 256]
//   d_in[1]: op_idx          int32   [B, N]   = [4096, 64]
// Output: float32 [B, D] = [4096, 256]
//
// out[b, :] = sum_{n: op[b,n]!=5} h[b,n,:] / max(count, 1)
//
// Shape: 2 CTAs per graph (disjoint column halves -> no recombination),
// 128 threads each: 4 row-groups x 32 float4-columns, 16 strided rows/thread.
// Grid = 8192, 16 CTAs/SM = 2048 thr/SM. Halved work quantum => halved drain tail.

#define SKIP_OP 5
#define NNODES  64
#define DIM     256
#define DIM4    (DIM / 4)      // 64 float4 per row
#define HALF4   (DIM4 / 2)     // 32 float4 columns per CTA

__global__ __launch_bounds__(128, 16)
void readout_kernel(const float* __restrict__ h,
                    const int* __restrict__ op,
                    float* __restrict__ out)
{
    const int b    = blockIdx.x >> 1;          // graph id
    const int half = blockIdx.x & 1;           // column half 0/1
    const int tid  = threadIdx.x;

    __shared__ float  mask[NNODES];
    __shared__ float4 partial[4][HALF4];
    __shared__ int    wcnt[2];

    // Stage mask + count via ballot (warps 0,1 cover the 64 nodes).
    if (tid < NNODES) {
        const bool keep = (op[(size_t)b * NNODES + tid] != SKIP_OP);
        mask[tid] = keep ? 1.0f : 0.0f;
        const unsigned bal = __ballot_sync(0xffffffffu, keep);
        if ((tid & 31) == 0) wcnt[tid >> 5] = __popc(bal);
    }
    __syncthreads();

    const int col = half * HALF4 + (tid & (HALF4 - 1));  // float4 column 0..63
    const int g   = tid >> 5;                            // row group 0..3

    const float4* hp = reinterpret_cast<const float4*>(
        h + (size_t)b * NNODES * DIM);

    float4 acc = make_float4(0.f, 0.f, 0.f, 0.f);

    // 16 strided iterations; each warp reads 512 B contiguous per step.
#pragma unroll
    for (int r = g; r < NNODES; r += 4) {
        const float  m = mask[r];
        const float4 v = __ldcs(&hp[r * DIM4 + col]);
        acc.x = fmaf(m, v.x, acc.x);
        acc.y = fmaf(m, v.y, acc.y);
        acc.z = fmaf(m, v.z, acc.z);
        acc.w = fmaf(m, v.w, acc.w);
    }

    partial[g][tid & (HALF4 - 1)] = acc;
    __syncthreads();

    if (tid < HALF4) {
        const float cnt = (float)(wcnt[0] + wcnt[1]);
        const float inv = 1.0f / fmaxf(cnt, 1.0f);

        float4 s0 = partial[0][tid];
        float4 s1 = partial[1][tid];
        float4 s2 = partial[2][tid];
        float4 s3 = partial[3][tid];
        float4 s;
        s.x = (s0.x + s1.x + s2.x + s3.x) * inv;
        s.y = (s0.y + s1.y + s2.y + s3.y) * inv;
        s.z = (s0.z + s1.z + s2.z + s3.z) * inv;
        s.w = (s0.w + s1.w + s2.w + s3.w) * inv;

        __stcs(&reinterpret_cast<float4*>(out + (size_t)b * DIM)
                   [half * HALF4 + tid], s);
    }
}

extern "C" void kernel_launch(void* const* d_in, const int* in_sizes, int n_in,
                              void* d_out, int out_size)
{
    const float* h  = (const float*)d_in[0];
    const int*   op = (const int*)d_in[1];
    float*       o  = (float*)d_out;

    const int B = in_sizes[1] / NNODES;   // op_idx has B*N elements

    readout_kernel<<<B * 2, 128>>>(h, op, o);
}